// round 6
// baseline (speedup 1.0000x reference)
#include <cuda_runtime.h>

// ---------------------------------------------------------------------------
// EngramModule fused forward.
// Stage 1: per-slot projection tables. 128x128 tile / 8x8 microtile GEMM,
//          packed fma.rn.f32x2 inner loop (2 MACs per instruction).
// Stage 2: warp-per-(token-run, stream), software-pipelined gathers with
//          reduced-current-token state to maximize occupancy.
// ---------------------------------------------------------------------------

#define Bq    8
#define Tq    4096
#define CHq   512
#define R_TOK 32
#define CHUNKS (Tq / R_TOK)   // 128

__device__ float g_Vtab[16384 * 128];   // 8 MB
__device__ float g_Ktab[16384 * 512];   // 32 MB

__device__ __forceinline__ unsigned long long pk2(float lo, float hi) {
    unsigned long long r;
    asm("mov.b64 %0, {%1, %2};" : "=l"(r) : "f"(lo), "f"(hi));
    return r;
}
__device__ __forceinline__ void upk2(float& lo, float& hi, unsigned long long v) {
    asm("mov.b64 {%0, %1}, %2;" : "=f"(lo), "=f"(hi) : "l"(v));
}
__device__ __forceinline__ void ffma2(unsigned long long& d,
                                      unsigned long long a,
                                      unsigned long long b) {
    asm("fma.rn.f32x2 %0, %1, %2, %0;" : "+l"(d) : "l"(a), "l"(b));
}

// ---------------------------------------------------------------------------
// Stage 1: 4 group-GEMMs of (4096 x 64) @ (64 x 640), fp32, FFMA2 core.
// ---------------------------------------------------------------------------
__global__ void __launch_bounds__(256) precompute_kernel(
    const float* __restrict__ emb,      // (16384, 64)
    const float* __restrict__ valW,     // (128, 256)
    const float* __restrict__ keyW,     // (512, 256)
    const float* __restrict__ valb,     // (128)
    const float* __restrict__ keyb)     // (512)
{
    __shared__ __align__(16) float As[16][132];
    __shared__ __align__(16) float Bs[16][132];

    const int tid  = threadIdx.x;
    const int nblk = blockIdx.x;   // 0..4  (col tile)
    const int mblk = blockIdx.y;   // 0..31 (row tile within group)
    const int g    = blockIdx.z;   // 0..3

    const int row0 = (tid >> 4) << 3;
    const int col0 = (tid & 15) << 3;

    // packed accumulators: acc2[i][j] holds cols (2j, 2j+1) for row i
    unsigned long long acc2[8][4];
#pragma unroll
    for (int i = 0; i < 8; i++)
#pragma unroll
        for (int j = 0; j < 4; j++) acc2[i][j] = 0ull;

    const float* abase = emb + (size_t)((g << 12) + (mblk << 7)) * 64;
    const float* bbase = ((nblk == 0) ? valW
                                      : keyW + (size_t)(nblk - 1) * 128 * 256)
                         + g * 64;

#pragma unroll
    for (int kc = 0; kc < 4; kc++) {
#pragma unroll
        for (int u = 0; u < 2; u++) {
            const int f   = tid + (u << 8);
            const int row = f >> 2;
            const int j   = (f & 3) << 2;
            float4 av = *(const float4*)(abase + row * 64  + kc * 16 + j);
            float4 bv = *(const float4*)(bbase + row * 256 + kc * 16 + j);
            As[j + 0][row] = av.x; As[j + 1][row] = av.y;
            As[j + 2][row] = av.z; As[j + 3][row] = av.w;
            Bs[j + 0][row] = bv.x; Bs[j + 1][row] = bv.y;
            Bs[j + 2][row] = bv.z; Bs[j + 3][row] = bv.w;
        }
        __syncthreads();
#pragma unroll
        for (int e = 0; e < 16; e++) {
            float4 a0 = *(const float4*)&As[e][row0];
            float4 a1 = *(const float4*)&As[e][row0 + 4];
            float4 b0 = *(const float4*)&Bs[e][col0];
            float4 b1 = *(const float4*)&Bs[e][col0 + 4];
            unsigned long long bj[4] = {pk2(b0.x, b0.y), pk2(b0.z, b0.w),
                                        pk2(b1.x, b1.y), pk2(b1.z, b1.w)};
            float ar[8] = {a0.x, a0.y, a0.z, a0.w, a1.x, a1.y, a1.z, a1.w};
#pragma unroll
            for (int i = 0; i < 8; i++) {
                unsigned long long ai = pk2(ar[i], ar[i]);
#pragma unroll
                for (int j = 0; j < 4; j++)
                    ffma2(acc2[i][j], ai, bj[j]);
            }
        }
        __syncthreads();
    }

    const int slot0 = (g << 12) + (mblk << 7) + row0;
    const float* bias = (nblk == 0) ? (valb + col0) : (keyb + (nblk - 1) * 128 + col0);
    float4 bia = *(const float4*)(bias);
    float4 bib = *(const float4*)(bias + 4);

#pragma unroll
    for (int i = 0; i < 8; i++) {
        float r[8];
        upk2(r[0], r[1], acc2[i][0]);
        upk2(r[2], r[3], acc2[i][1]);
        upk2(r[4], r[5], acc2[i][2]);
        upk2(r[6], r[7], acc2[i][3]);
        float4 o0 = make_float4(r[0] + 0.25f * bia.x, r[1] + 0.25f * bia.y,
                                r[2] + 0.25f * bia.z, r[3] + 0.25f * bia.w);
        float4 o1 = make_float4(r[4] + 0.25f * bib.x, r[5] + 0.25f * bib.y,
                                r[6] + 0.25f * bib.z, r[7] + 0.25f * bib.w);
        float* dst = (nblk == 0)
            ? g_Vtab + (size_t)(slot0 + i) * 128 + col0
            : g_Ktab + (size_t)(slot0 + i) * 512 + (nblk - 1) * 128 + col0;
        *(float4*)(dst)     = o0;
        *(float4*)(dst + 4) = o1;
    }
}

// ---------------------------------------------------------------------------
// Stage 2 main kernel. Block = 128 threads = 4 stream-warps of one chunk.
// Pipeline: raw gathers for t+1 issued before compute(t); current token kept
// only in reduced form (kr, vb, q) to cut live registers.
// ---------------------------------------------------------------------------
struct Raw {
    float4 k0, k1, k2, k3;
    float4 v0, v1, v2, v3;
};

__global__ void __launch_bounds__(128, 5) engram_main_kernel(
    const float* __restrict__ x,        // (B,T,4,128)
    const int*   __restrict__ ids,      // (B,T)
    const int*   __restrict__ mult,     // (2,2,3)
    const float* __restrict__ wq,       // (4,128)
    const float* __restrict__ wk,       // (4,128)
    const float* __restrict__ convw,    // (512,4)
    const float* __restrict__ convn,    // (4,128)
    float*       __restrict__ out)      // (B,T,4,128)
{
    const int stream = threadIdx.x >> 5;
    const int lane   = threadIdx.x & 31;
    const int b      = blockIdx.x >> 7;
    const int chunk  = blockIdx.x & 127;
    const int t0     = chunk * R_TOK;

    const int c = stream * 128 + lane * 4;
    const int d = lane * 4;

    const float4 wq4  = *(const float4*)(wq + c);
    const float4 wk4  = *(const float4*)(wk + c);
    const float4 wqk4 = make_float4(wq4.x * wk4.x, wq4.y * wk4.y,
                                    wq4.z * wk4.z, wq4.w * wk4.w);
    const float4 cvn4 = *(const float4*)(convn + c);
    const float4 cwA  = *(const float4*)(convw + (c + 0) * 4);
    const float4 cwB  = *(const float4*)(convw + (c + 1) * 4);
    const float4 cwC  = *(const float4*)(convw + (c + 2) * 4);
    const float4 cwD  = *(const float4*)(convw + (c + 3) * 4);

    const int m00 = mult[0],  m01 = mult[1];
    const int m10 = mult[3],  m11 = mult[4];
    const int m20 = mult[6],  m21 = mult[7],  m22 = mult[8];
    const int m30 = mult[9],  m31 = mult[10], m32 = mult[11];

    const float inv128     = 0.0078125f;
    const float eps        = 1.1920929e-7f;
    const float invsqrt128 = 0.08838834764831845f;

    const int    idBase = b * Tq;
    const float* xBase  = x   + (size_t)idBase * CHq + c;
    float*       oBase  = out + (size_t)idBase * CHq + c;

    float4 h1 = make_float4(0.f, 0.f, 0.f, 0.f);
    float4 h2 = h1;
    float4 h3 = h1;

    auto gatherRaw = [&](Raw& T, int ia, int ib, int ic) {
        const int h0i = (((ib * m00) ^ (ic * m01)) & 4095);
        const int h1i = (((ib * m10) ^ (ic * m11)) & 4095) + 4096;
        const int h2i = (((ia * m20) ^ (ib * m21) ^ (ic * m22)) & 4095) + 8192;
        const int h3i = (((ia * m30) ^ (ib * m31) ^ (ic * m32)) & 4095) + 12288;
        T.k0 = __ldg((const float4*)(g_Ktab + (size_t)h0i * 512 + c));
        T.k1 = __ldg((const float4*)(g_Ktab + (size_t)h1i * 512 + c));
        T.k2 = __ldg((const float4*)(g_Ktab + (size_t)h2i * 512 + c));
        T.k3 = __ldg((const float4*)(g_Ktab + (size_t)h3i * 512 + c));
        T.v0 = __ldg((const float4*)(g_Vtab + (size_t)h0i * 128 + d));
        T.v1 = __ldg((const float4*)(g_Vtab + (size_t)h1i * 128 + d));
        T.v2 = __ldg((const float4*)(g_Vtab + (size_t)h2i * 128 + d));
        T.v3 = __ldg((const float4*)(g_Vtab + (size_t)h3i * 128 + d));
    };

    auto reduceRaw = [&](const Raw& T, float4& kr, float4& vb) {
        kr.x = (T.k0.x + T.k1.x) + (T.k2.x + T.k3.x);
        kr.y = (T.k0.y + T.k1.y) + (T.k2.y + T.k3.y);
        kr.z = (T.k0.z + T.k1.z) + (T.k2.z + T.k3.z);
        kr.w = (T.k0.w + T.k1.w) + (T.k2.w + T.k3.w);
        vb.x = (T.v0.x + T.v1.x) + (T.v2.x + T.v3.x);
        vb.y = (T.v0.y + T.v1.y) + (T.v2.y + T.v3.y);
        vb.z = (T.v0.z + T.v1.z) + (T.v2.z + T.v3.z);
        vb.w = (T.v0.w + T.v1.w) + (T.v2.w + T.v3.w);
    };

    auto compute = [&](const float4& kr, const float4& vb, const float4& q,
                       int t, bool store) {
        float p0 = q.x * q.x + q.y * q.y + q.z * q.z + q.w * q.w;
        float p1 = kr.x * kr.x + kr.y * kr.y + kr.z * kr.z + kr.w * kr.w;
        float p2 = q.x * kr.x * wqk4.x + q.y * kr.y * wqk4.y
                 + q.z * kr.z * wqk4.z + q.w * kr.w * wqk4.w;
        float p3 = vb.x * vb.x + vb.y * vb.y + vb.z * vb.z + vb.w * vb.w;

        const bool lo = (lane < 16);
        float ea = __shfl_xor_sync(0xffffffffu, p0, 16);
        float eb = __shfl_xor_sync(0xffffffffu, p2, 16);
        float aa = lo ? (p0 + ea) : (p2 + eb);
        float ec = __shfl_xor_sync(0xffffffffu, p1, 16);
        float ed = __shfl_xor_sync(0xffffffffu, p3, 16);
        float bb = lo ? (p1 + ec) : (p3 + ed);
#pragma unroll
        for (int off = 8; off; off >>= 1) {
            aa += __shfl_xor_sync(0xffffffffu, aa, off);
            bb += __shfl_xor_sync(0xffffffffu, bb, off);
        }
        const float a2 = __shfl_xor_sync(0xffffffffu, aa, 16);
        const float b2 = __shfl_xor_sync(0xffffffffu, bb, 16);
        const float sq  = lo ? aa : a2;
        const float sk  = lo ? bb : b2;
        const float sqk = lo ? a2 : aa;
        const float svb = lo ? b2 : bb;

        const float rsq   = rsqrtf(sq * inv128 + eps);
        const float rsk   = rsqrtf(sk * inv128 + eps);
        const float score = sqk * rsq * rsk * invsqrt128;
        const float gate  = __fdividef(1.f, 1.f + __expf(-score));
        const float rr    = rsqrtf(gate * gate * svb * inv128 + eps) * gate;

        float4 xn;
        xn.x = vb.x * rr * cvn4.x;  xn.y = vb.y * rr * cvn4.y;
        xn.z = vb.z * rr * cvn4.z;  xn.w = vb.w * rr * cvn4.w;

        if (store) {
            float4 y;
            y.x = cwA.x * h3.x + cwA.y * h2.x + cwA.z * h1.x + cwA.w * xn.x;
            y.y = cwB.x * h3.y + cwB.y * h2.y + cwB.z * h1.y + cwB.w * xn.y;
            y.z = cwC.x * h3.z + cwC.y * h2.z + cwC.z * h1.z + cwC.w * xn.z;
            y.w = cwD.x * h3.w + cwD.y * h2.w + cwD.z * h1.w + cwD.w * xn.w;
            y.x = __fdividef(y.x, 1.f + __expf(-y.x));
            y.y = __fdividef(y.y, 1.f + __expf(-y.y));
            y.z = __fdividef(y.z, 1.f + __expf(-y.z));
            y.w = __fdividef(y.w, 1.f + __expf(-y.w));
            float4 o;
            o.x = vb.x * gate + y.x;  o.y = vb.y * gate + y.y;
            o.z = vb.z * gate + y.z;  o.w = vb.w * gate + y.w;
            *(float4*)(oBase + (size_t)t * CHq) = o;
        }
        h3 = h2; h2 = h1; h1 = xn;
    };

    int ia = (t0 - 5 >= 0) ? __ldg(ids + idBase + t0 - 5) : 0;
    int ib = (t0 - 4 >= 0) ? __ldg(ids + idBase + t0 - 4) : 0;

    // ---- halo prologue: tokens t0-3 .. t0-1 (no store, unpipelined) ----
#pragma unroll
    for (int tt = -3; tt < 0; tt++) {
        const int t  = t0 + tt;
        const int ic = (t >= 0) ? __ldg(ids + idBase + t) : 0;
        if (t >= 0) {
            Raw P;
            gatherRaw(P, ia, ib, ic);
            float4 kr, vb;
            reduceRaw(P, kr, vb);
            float4 q = *(const float4*)(xBase + (size_t)t * CHq);
            compute(kr, vb, q, t, false);
        }
        ia = ib; ib = ic;
    }

    // ---- pipelined main loop ----
    int ic = __ldg(ids + idBase + t0);
    float4 kr, vb;
    {
        Raw P;
        gatherRaw(P, ia, ib, ic);
        reduceRaw(P, kr, vb);
    }
    float4 qc = *(const float4*)(xBase + (size_t)t0 * CHq);

    for (int tt = 0; tt < R_TOK; tt++) {
        const int t = t0 + tt;
        Raw N;
        float4 qn;
        int in_ = ic;
        const bool more = (tt + 1 < R_TOK);
        if (more) {
            in_ = __ldg(ids + idBase + t + 1);
            gatherRaw(N, ib, ic, in_);             // issue loads
            qn = *(const float4*)(xBase + (size_t)(t + 1) * CHq);
        }
        compute(kr, vb, qc, t, true);              // overlap with loads
        if (more) {
            reduceRaw(N, kr, vb);                  // waits land here
            qc = qn;
        }
        ia = ib; ib = ic; ic = in_;
    }
}

// ---------------------------------------------------------------------------
extern "C" void kernel_launch(void* const* d_in, const int* in_sizes, int n_in,
                              void* d_out, int out_size)
{
    const float* x          = (const float*)d_in[0];
    const int*   input_ids  = (const int*)  d_in[1];
    const int*   multipliers= (const int*)  d_in[2];
    const float* embedding  = (const float*)d_in[3];
    const float* val_W      = (const float*)d_in[4];
    const float* val_b      = (const float*)d_in[5];
    const float* key_W      = (const float*)d_in[6];
    const float* key_b      = (const float*)d_in[7];
    const float* normq_w    = (const float*)d_in[8];
    const float* normk_w    = (const float*)d_in[9];
    const float* conv_w     = (const float*)d_in[10];
    const float* convnorm_w = (const float*)d_in[11];
    float* out = (float*)d_out;

    dim3 gp(5, 32, 4);
    precompute_kernel<<<gp, 256>>>(embedding, val_W, key_W, val_b, key_b);

    engram_main_kernel<<<Bq * CHUNKS, 128>>>(
        x, input_ids, multipliers,
        normq_w, normk_w, conv_w, convnorm_w, out);
}

// round 7
// speedup vs baseline: 1.2621x; 1.2621x over previous
#include <cuda_runtime.h>

// ---------------------------------------------------------------------------
// EngramModule fused forward.
// Stage 1: per-slot projection tables. 128x128 tile / 8x8 microtile GEMM,
//          packed fma.rn.f32x2 inner loop.
// Stage 2: warp-per-(token-run, stream), one-token software pipeline
//          (R4 structure: prefetched Tok consumed at top of next iteration),
//          5 blocks/SM.
// ---------------------------------------------------------------------------

#define Bq    8
#define Tq    4096
#define CHq   512
#define R_TOK 32
#define CHUNKS (Tq / R_TOK)   // 128

__device__ float g_Vtab[16384 * 128];   // 8 MB
__device__ float g_Ktab[16384 * 512];   // 32 MB

__device__ __forceinline__ unsigned long long pk2(float lo, float hi) {
    unsigned long long r;
    asm("mov.b64 %0, {%1, %2};" : "=l"(r) : "f"(lo), "f"(hi));
    return r;
}
__device__ __forceinline__ void upk2(float& lo, float& hi, unsigned long long v) {
    asm("mov.b64 {%0, %1}, %2;" : "=f"(lo), "=f"(hi) : "l"(v));
}
__device__ __forceinline__ void ffma2(unsigned long long& d,
                                      unsigned long long a,
                                      unsigned long long b) {
    asm("fma.rn.f32x2 %0, %1, %2, %0;" : "+l"(d) : "l"(a), "l"(b));
}

// ---------------------------------------------------------------------------
// Stage 1: 4 group-GEMMs of (4096 x 64) @ (64 x 640), fp32, FFMA2 core.
// ---------------------------------------------------------------------------
__global__ void __launch_bounds__(256) precompute_kernel(
    const float* __restrict__ emb,      // (16384, 64)
    const float* __restrict__ valW,     // (128, 256)
    const float* __restrict__ keyW,     // (512, 256)
    const float* __restrict__ valb,     // (128)
    const float* __restrict__ keyb)     // (512)
{
    __shared__ __align__(16) float As[16][132];
    __shared__ __align__(16) float Bs[16][132];

    const int tid  = threadIdx.x;
    const int nblk = blockIdx.x;   // 0..4  (col tile)
    const int mblk = blockIdx.y;   // 0..31 (row tile within group)
    const int g    = blockIdx.z;   // 0..3

    const int row0 = (tid >> 4) << 3;
    const int col0 = (tid & 15) << 3;

    unsigned long long acc2[8][4];
#pragma unroll
    for (int i = 0; i < 8; i++)
#pragma unroll
        for (int j = 0; j < 4; j++) acc2[i][j] = 0ull;

    const float* abase = emb + (size_t)((g << 12) + (mblk << 7)) * 64;
    const float* bbase = ((nblk == 0) ? valW
                                      : keyW + (size_t)(nblk - 1) * 128 * 256)
                         + g * 64;

#pragma unroll
    for (int kc = 0; kc < 4; kc++) {
#pragma unroll
        for (int u = 0; u < 2; u++) {
            const int f   = tid + (u << 8);
            const int row = f >> 2;
            const int j   = (f & 3) << 2;
            float4 av = *(const float4*)(abase + row * 64  + kc * 16 + j);
            float4 bv = *(const float4*)(bbase + row * 256 + kc * 16 + j);
            As[j + 0][row] = av.x; As[j + 1][row] = av.y;
            As[j + 2][row] = av.z; As[j + 3][row] = av.w;
            Bs[j + 0][row] = bv.x; Bs[j + 1][row] = bv.y;
            Bs[j + 2][row] = bv.z; Bs[j + 3][row] = bv.w;
        }
        __syncthreads();
#pragma unroll
        for (int e = 0; e < 16; e++) {
            float4 a0 = *(const float4*)&As[e][row0];
            float4 a1 = *(const float4*)&As[e][row0 + 4];
            float4 b0 = *(const float4*)&Bs[e][col0];
            float4 b1 = *(const float4*)&Bs[e][col0 + 4];
            unsigned long long bj[4] = {pk2(b0.x, b0.y), pk2(b0.z, b0.w),
                                        pk2(b1.x, b1.y), pk2(b1.z, b1.w)};
            float ar[8] = {a0.x, a0.y, a0.z, a0.w, a1.x, a1.y, a1.z, a1.w};
#pragma unroll
            for (int i = 0; i < 8; i++) {
                unsigned long long ai = pk2(ar[i], ar[i]);
#pragma unroll
                for (int j = 0; j < 4; j++)
                    ffma2(acc2[i][j], ai, bj[j]);
            }
        }
        __syncthreads();
    }

    const int slot0 = (g << 12) + (mblk << 7) + row0;
    const float* bias = (nblk == 0) ? (valb + col0) : (keyb + (nblk - 1) * 128 + col0);
    float4 bia = *(const float4*)(bias);
    float4 bib = *(const float4*)(bias + 4);

#pragma unroll
    for (int i = 0; i < 8; i++) {
        float r[8];
        upk2(r[0], r[1], acc2[i][0]);
        upk2(r[2], r[3], acc2[i][1]);
        upk2(r[4], r[5], acc2[i][2]);
        upk2(r[6], r[7], acc2[i][3]);
        float4 o0 = make_float4(r[0] + 0.25f * bia.x, r[1] + 0.25f * bia.y,
                                r[2] + 0.25f * bia.z, r[3] + 0.25f * bia.w);
        float4 o1 = make_float4(r[4] + 0.25f * bib.x, r[5] + 0.25f * bib.y,
                                r[6] + 0.25f * bib.z, r[7] + 0.25f * bib.w);
        float* dst = (nblk == 0)
            ? g_Vtab + (size_t)(slot0 + i) * 128 + col0
            : g_Ktab + (size_t)(slot0 + i) * 512 + (nblk - 1) * 128 + col0;
        *(float4*)(dst)     = o0;
        *(float4*)(dst + 4) = o1;
    }
}

// ---------------------------------------------------------------------------
// Stage 2 main kernel (R4 structure). Block = 128 threads = 4 stream-warps
// of one chunk. Prefetched Tok(t+1) issued before compute(t), consumed at
// the top of the next iteration.
// ---------------------------------------------------------------------------
struct Tok {
    float4 k0, k1, k2, k3;
    float4 v0, v1, v2, v3;
    float4 q;
};

__global__ void __launch_bounds__(128, 5) engram_main_kernel(
    const float* __restrict__ x,        // (B,T,4,128)
    const int*   __restrict__ ids,      // (B,T)
    const int*   __restrict__ mult,     // (2,2,3)
    const float* __restrict__ wq,       // (4,128)
    const float* __restrict__ wk,       // (4,128)
    const float* __restrict__ convw,    // (512,4)
    const float* __restrict__ convn,    // (4,128)
    float*       __restrict__ out)      // (B,T,4,128)
{
    const int stream = threadIdx.x >> 5;
    const int lane   = threadIdx.x & 31;
    const int b      = blockIdx.x >> 7;
    const int chunk  = blockIdx.x & 127;
    const int t0     = chunk * R_TOK;

    const int c = stream * 128 + lane * 4;
    const int d = lane * 4;

    const float4 wq4  = *(const float4*)(wq + c);
    const float4 wk4  = *(const float4*)(wk + c);
    const float4 wqk4 = make_float4(wq4.x * wk4.x, wq4.y * wk4.y,
                                    wq4.z * wk4.z, wq4.w * wk4.w);
    const float4 cvn4 = *(const float4*)(convn + c);
    const float4 cwA  = *(const float4*)(convw + (c + 0) * 4);
    const float4 cwB  = *(const float4*)(convw + (c + 1) * 4);
    const float4 cwC  = *(const float4*)(convw + (c + 2) * 4);
    const float4 cwD  = *(const float4*)(convw + (c + 3) * 4);

    const int m00 = mult[0],  m01 = mult[1];
    const int m10 = mult[3],  m11 = mult[4];
    const int m20 = mult[6],  m21 = mult[7],  m22 = mult[8];
    const int m30 = mult[9],  m31 = mult[10], m32 = mult[11];

    const float inv128     = 0.0078125f;
    const float eps        = 1.1920929e-7f;
    const float invsqrt128 = 0.08838834764831845f;

    const int    idBase = b * Tq;
    const float* xBase  = x   + (size_t)idBase * CHq + c;
    float*       oBase  = out + (size_t)idBase * CHq + c;

    float4 h1 = make_float4(0.f, 0.f, 0.f, 0.f);
    float4 h2 = h1;
    float4 h3 = h1;

    auto gather = [&](Tok& T, int ia, int ib, int ic, int t) {
        const int h0i = (((ib * m00) ^ (ic * m01)) & 4095);
        const int h1i = (((ib * m10) ^ (ic * m11)) & 4095) + 4096;
        const int h2i = (((ia * m20) ^ (ib * m21) ^ (ic * m22)) & 4095) + 8192;
        const int h3i = (((ia * m30) ^ (ib * m31) ^ (ic * m32)) & 4095) + 12288;
        T.k0 = __ldg((const float4*)(g_Ktab + (size_t)h0i * 512 + c));
        T.k1 = __ldg((const float4*)(g_Ktab + (size_t)h1i * 512 + c));
        T.k2 = __ldg((const float4*)(g_Ktab + (size_t)h2i * 512 + c));
        T.k3 = __ldg((const float4*)(g_Ktab + (size_t)h3i * 512 + c));
        T.v0 = __ldg((const float4*)(g_Vtab + (size_t)h0i * 128 + d));
        T.v1 = __ldg((const float4*)(g_Vtab + (size_t)h1i * 128 + d));
        T.v2 = __ldg((const float4*)(g_Vtab + (size_t)h2i * 128 + d));
        T.v3 = __ldg((const float4*)(g_Vtab + (size_t)h3i * 128 + d));
        T.q  = *(const float4*)(xBase + (size_t)t * CHq);
    };

    auto compute = [&](const Tok& T, int t, bool store) {
        float4 kr, vb;
        kr.x = (T.k0.x + T.k1.x) + (T.k2.x + T.k3.x);
        kr.y = (T.k0.y + T.k1.y) + (T.k2.y + T.k3.y);
        kr.z = (T.k0.z + T.k1.z) + (T.k2.z + T.k3.z);
        kr.w = (T.k0.w + T.k1.w) + (T.k2.w + T.k3.w);
        vb.x = (T.v0.x + T.v1.x) + (T.v2.x + T.v3.x);
        vb.y = (T.v0.y + T.v1.y) + (T.v2.y + T.v3.y);
        vb.z = (T.v0.z + T.v1.z) + (T.v2.z + T.v3.z);
        vb.w = (T.v0.w + T.v1.w) + (T.v2.w + T.v3.w);

        float p0 = T.q.x * T.q.x + T.q.y * T.q.y + T.q.z * T.q.z + T.q.w * T.q.w;
        float p1 = kr.x * kr.x + kr.y * kr.y + kr.z * kr.z + kr.w * kr.w;
        float p2 = T.q.x * kr.x * wqk4.x + T.q.y * kr.y * wqk4.y
                 + T.q.z * kr.z * wqk4.z + T.q.w * kr.w * wqk4.w;
        float p3 = vb.x * vb.x + vb.y * vb.y + vb.z * vb.z + vb.w * vb.w;

        const bool lo = (lane < 16);
        float ea = __shfl_xor_sync(0xffffffffu, p0, 16);
        float eb = __shfl_xor_sync(0xffffffffu, p2, 16);
        float aa = lo ? (p0 + ea) : (p2 + eb);
        float ec = __shfl_xor_sync(0xffffffffu, p1, 16);
        float ed = __shfl_xor_sync(0xffffffffu, p3, 16);
        float bb = lo ? (p1 + ec) : (p3 + ed);
#pragma unroll
        for (int off = 8; off; off >>= 1) {
            aa += __shfl_xor_sync(0xffffffffu, aa, off);
            bb += __shfl_xor_sync(0xffffffffu, bb, off);
        }
        const float a2 = __shfl_xor_sync(0xffffffffu, aa, 16);
        const float b2 = __shfl_xor_sync(0xffffffffu, bb, 16);
        const float sq  = lo ? aa : a2;
        const float sk  = lo ? bb : b2;
        const float sqk = lo ? a2 : aa;
        const float svb = lo ? b2 : bb;

        const float rsq   = rsqrtf(sq * inv128 + eps);
        const float rsk   = rsqrtf(sk * inv128 + eps);
        const float score = sqk * rsq * rsk * invsqrt128;
        const float gate  = __fdividef(1.f, 1.f + __expf(-score));
        const float rr    = rsqrtf(gate * gate * svb * inv128 + eps) * gate;

        float4 xn;
        xn.x = vb.x * rr * cvn4.x;  xn.y = vb.y * rr * cvn4.y;
        xn.z = vb.z * rr * cvn4.z;  xn.w = vb.w * rr * cvn4.w;

        if (store) {
            float4 y;
            y.x = cwA.x * h3.x + cwA.y * h2.x + cwA.z * h1.x + cwA.w * xn.x;
            y.y = cwB.x * h3.y + cwB.y * h2.y + cwB.z * h1.y + cwB.w * xn.y;
            y.z = cwC.x * h3.z + cwC.y * h2.z + cwC.z * h1.z + cwC.w * xn.z;
            y.w = cwD.x * h3.w + cwD.y * h2.w + cwD.z * h1.w + cwD.w * xn.w;
            y.x = __fdividef(y.x, 1.f + __expf(-y.x));
            y.y = __fdividef(y.y, 1.f + __expf(-y.y));
            y.z = __fdividef(y.z, 1.f + __expf(-y.z));
            y.w = __fdividef(y.w, 1.f + __expf(-y.w));
            float4 o;
            o.x = vb.x * gate + y.x;  o.y = vb.y * gate + y.y;
            o.z = vb.z * gate + y.z;  o.w = vb.w * gate + y.w;
            *(float4*)(oBase + (size_t)t * CHq) = o;
        }
        h3 = h2; h2 = h1; h1 = xn;
    };

    int ia = (t0 - 5 >= 0) ? __ldg(ids + idBase + t0 - 5) : 0;
    int ib = (t0 - 4 >= 0) ? __ldg(ids + idBase + t0 - 4) : 0;

    // ---- halo prologue: tokens t0-3 .. t0-1 (no store, unpipelined) ----
#pragma unroll
    for (int tt = -3; tt < 0; tt++) {
        const int t  = t0 + tt;
        const int ic = (t >= 0) ? __ldg(ids + idBase + t) : 0;
        if (t >= 0) {
            Tok P;
            gather(P, ia, ib, ic, t);
            compute(P, t, false);
        }
        ia = ib; ib = ic;
    }

    // ---- pipelined main loop: tokens t0 .. t0+31 ----
    int ic = __ldg(ids + idBase + t0);
    Tok cur;
    gather(cur, ia, ib, ic, t0);

    for (int tt = 0; tt < R_TOK; tt++) {
        const int t = t0 + tt;
        Tok nxt;
        int in_ = ic;
        if (tt + 1 < R_TOK) {
            in_ = __ldg(ids + idBase + t + 1);
            gather(nxt, ib, ic, in_, t + 1);   // issue before compute(cur)
        }
        compute(cur, t, true);
        ia = ib; ib = ic; ic = in_;
        cur = nxt;
    }
}

// ---------------------------------------------------------------------------
extern "C" void kernel_launch(void* const* d_in, const int* in_sizes, int n_in,
                              void* d_out, int out_size)
{
    const float* x          = (const float*)d_in[0];
    const int*   input_ids  = (const int*)  d_in[1];
    const int*   multipliers= (const int*)  d_in[2];
    const float* embedding  = (const float*)d_in[3];
    const float* val_W      = (const float*)d_in[4];
    const float* val_b      = (const float*)d_in[5];
    const float* key_W      = (const float*)d_in[6];
    const float* key_b      = (const float*)d_in[7];
    const float* normq_w    = (const float*)d_in[8];
    const float* normk_w    = (const float*)d_in[9];
    const float* conv_w     = (const float*)d_in[10];
    const float* convnorm_w = (const float*)d_in[11];
    float* out = (float*)d_out;

    dim3 gp(5, 32, 4);
    precompute_kernel<<<gp, 256>>>(embedding, val_W, key_W, val_b, key_b);

    engram_main_kernel<<<Bq * CHUNKS, 128>>>(
        x, input_ids, multipliers,
        normq_w, normk_w, conv_w, convnorm_w, out);
}

// round 8
// speedup vs baseline: 1.3607x; 1.0780x over previous
#include <cuda_runtime.h>

// ---------------------------------------------------------------------------
// EngramModule fused forward.
// Stage 1: per-slot projection tables. 128x64 tiles, 128 threads, 8x8
//          microtile, packed fma.rn.f32x2 inner loop. Fine-grained grid
//          (1280 blocks) to kill the wave-quantization tail.
// Stage 2: warp-per-(16-token run, stream), one-token software pipeline
//          (prefetched Tok consumed at top of next iteration). Grid 2048.
// ---------------------------------------------------------------------------

#define Bq    8
#define Tq    4096
#define CHq   512
#define R_TOK 16
#define CHUNKS (Tq / R_TOK)   // 256

__device__ float g_Vtab[16384 * 128];   // 8 MB
__device__ float g_Ktab[16384 * 512];   // 32 MB

__device__ __forceinline__ unsigned long long pk2(float lo, float hi) {
    unsigned long long r;
    asm("mov.b64 %0, {%1, %2};" : "=l"(r) : "f"(lo), "f"(hi));
    return r;
}
__device__ __forceinline__ void upk2(float& lo, float& hi, unsigned long long v) {
    asm("mov.b64 {%0, %1}, %2;" : "=f"(lo), "=f"(hi) : "l"(v));
}
__device__ __forceinline__ void ffma2(unsigned long long& d,
                                      unsigned long long a,
                                      unsigned long long b) {
    asm("fma.rn.f32x2 %0, %1, %2, %0;" : "+l"(d) : "l"(a), "l"(b));
}

// ---------------------------------------------------------------------------
// Stage 1: 4 group-GEMMs of (4096 x 64) @ (64 x 640), fp32, FFMA2 core.
// Block = 128 rows x 64 cols, 128 threads, 8x8 microtile, k-chunks of 16.
// Col tiles 0-1 -> val_W; tiles 2..9 -> key_W (boundary at 128 = 2 tiles).
// ---------------------------------------------------------------------------
__global__ void __launch_bounds__(128) precompute_kernel(
    const float* __restrict__ emb,      // (16384, 64)
    const float* __restrict__ valW,     // (128, 256)
    const float* __restrict__ keyW,     // (512, 256)
    const float* __restrict__ valb,     // (128)
    const float* __restrict__ keyb)     // (512)
{
    __shared__ __align__(16) float As[16][132];
    __shared__ __align__(16) float Bs[16][68];

    const int tid  = threadIdx.x;
    const int nblk = blockIdx.x;   // 0..9  (64-col tile)
    const int mblk = blockIdx.y;   // 0..31 (128-row tile within group)
    const int g    = blockIdx.z;   // 0..3

    const int row0 = (tid >> 3) << 3;   // 0..120
    const int col0 = (tid & 7) << 3;    // 0..56

    unsigned long long acc2[8][4];
#pragma unroll
    for (int i = 0; i < 8; i++)
#pragma unroll
        for (int j = 0; j < 4; j++) acc2[i][j] = 0ull;

    const int gcol0 = nblk << 6;        // global col of tile start
    const float* abase = emb + (size_t)((g << 12) + (mblk << 7)) * 64;
    const float* bbase = ((gcol0 < 128) ? (valW + (size_t)gcol0 * 256)
                                        : (keyW + (size_t)(gcol0 - 128) * 256))
                         + g * 64;

#pragma unroll
    for (int kc = 0; kc < 4; kc++) {
        // A: 128 rows x 16 e  -> 4 float4/thread
#pragma unroll
        for (int u = 0; u < 4; u++) {
            const int f   = tid + (u << 7);     // 0..511
            const int row = f >> 2;             // 0..127
            const int j   = (f & 3) << 2;       // e-offset
            float4 av = *(const float4*)(abase + row * 64 + kc * 16 + j);
            As[j + 0][row] = av.x; As[j + 1][row] = av.y;
            As[j + 2][row] = av.z; As[j + 3][row] = av.w;
        }
        // B: 64 cols x 16 e -> 2 float4/thread
#pragma unroll
        for (int u = 0; u < 2; u++) {
            const int f   = tid + (u << 7);     // 0..255
            const int row = f >> 2;             // 0..63
            const int j   = (f & 3) << 2;
            float4 bv = *(const float4*)(bbase + row * 256 + kc * 16 + j);
            Bs[j + 0][row] = bv.x; Bs[j + 1][row] = bv.y;
            Bs[j + 2][row] = bv.z; Bs[j + 3][row] = bv.w;
        }
        __syncthreads();
#pragma unroll
        for (int e = 0; e < 16; e++) {
            float4 a0 = *(const float4*)&As[e][row0];
            float4 a1 = *(const float4*)&As[e][row0 + 4];
            float4 b0 = *(const float4*)&Bs[e][col0];
            float4 b1 = *(const float4*)&Bs[e][col0 + 4];
            unsigned long long bj[4] = {pk2(b0.x, b0.y), pk2(b0.z, b0.w),
                                        pk2(b1.x, b1.y), pk2(b1.z, b1.w)};
            float ar[8] = {a0.x, a0.y, a0.z, a0.w, a1.x, a1.y, a1.z, a1.w};
#pragma unroll
            for (int i = 0; i < 8; i++) {
                unsigned long long ai = pk2(ar[i], ar[i]);
#pragma unroll
                for (int j = 0; j < 4; j++)
                    ffma2(acc2[i][j], ai, bj[j]);
            }
        }
        __syncthreads();
    }

    const int slot0 = (g << 12) + (mblk << 7) + row0;
    const int gcol  = gcol0 + col0;
    const float* bias = (gcol < 128) ? (valb + gcol) : (keyb + gcol - 128);
    float4 bia = *(const float4*)(bias);
    float4 bib = *(const float4*)(bias + 4);

#pragma unroll
    for (int i = 0; i < 8; i++) {
        float r[8];
        upk2(r[0], r[1], acc2[i][0]);
        upk2(r[2], r[3], acc2[i][1]);
        upk2(r[4], r[5], acc2[i][2]);
        upk2(r[6], r[7], acc2[i][3]);
        float4 o0 = make_float4(r[0] + 0.25f * bia.x, r[1] + 0.25f * bia.y,
                                r[2] + 0.25f * bia.z, r[3] + 0.25f * bia.w);
        float4 o1 = make_float4(r[4] + 0.25f * bib.x, r[5] + 0.25f * bib.y,
                                r[6] + 0.25f * bib.z, r[7] + 0.25f * bib.w);
        float* dst = (gcol < 128)
            ? g_Vtab + (size_t)(slot0 + i) * 128 + gcol
            : g_Ktab + (size_t)(slot0 + i) * 512 + (gcol - 128);
        *(float4*)(dst)     = o0;
        *(float4*)(dst + 4) = o1;
    }
}

// ---------------------------------------------------------------------------
// Stage 2 main kernel. Block = 128 threads = 4 stream-warps of one 16-token
// chunk. Prefetched Tok(t+1) issued before compute(t), consumed at the top
// of the next iteration.
// ---------------------------------------------------------------------------
struct Tok {
    float4 k0, k1, k2, k3;
    float4 v0, v1, v2, v3;
    float4 q;
};

__global__ void __launch_bounds__(128, 5) engram_main_kernel(
    const float* __restrict__ x,        // (B,T,4,128)
    const int*   __restrict__ ids,      // (B,T)
    const int*   __restrict__ mult,     // (2,2,3)
    const float* __restrict__ wq,       // (4,128)
    const float* __restrict__ wk,       // (4,128)
    const float* __restrict__ convw,    // (512,4)
    const float* __restrict__ convn,    // (4,128)
    float*       __restrict__ out)      // (B,T,4,128)
{
    const int stream = threadIdx.x >> 5;
    const int lane   = threadIdx.x & 31;
    const int b      = blockIdx.x >> 8;       // CHUNKS = 256
    const int chunk  = blockIdx.x & 255;
    const int t0     = chunk * R_TOK;

    const int c = stream * 128 + lane * 4;
    const int d = lane * 4;

    const float4 wq4  = *(const float4*)(wq + c);
    const float4 wk4  = *(const float4*)(wk + c);
    const float4 wqk4 = make_float4(wq4.x * wk4.x, wq4.y * wk4.y,
                                    wq4.z * wk4.z, wq4.w * wk4.w);
    const float4 cvn4 = *(const float4*)(convn + c);
    const float4 cwA  = *(const float4*)(convw + (c + 0) * 4);
    const float4 cwB  = *(const float4*)(convw + (c + 1) * 4);
    const float4 cwC  = *(const float4*)(convw + (c + 2) * 4);
    const float4 cwD  = *(const float4*)(convw + (c + 3) * 4);

    const int m00 = mult[0],  m01 = mult[1];
    const int m10 = mult[3],  m11 = mult[4];
    const int m20 = mult[6],  m21 = mult[7],  m22 = mult[8];
    const int m30 = mult[9],  m31 = mult[10], m32 = mult[11];

    const float inv128     = 0.0078125f;
    const float eps        = 1.1920929e-7f;
    const float invsqrt128 = 0.08838834764831845f;

    const int    idBase = b * Tq;
    const float* xBase  = x   + (size_t)idBase * CHq + c;
    float*       oBase  = out + (size_t)idBase * CHq + c;

    float4 h1 = make_float4(0.f, 0.f, 0.f, 0.f);
    float4 h2 = h1;
    float4 h3 = h1;

    auto gather = [&](Tok& T, int ia, int ib, int ic, int t) {
        const int h0i = (((ib * m00) ^ (ic * m01)) & 4095);
        const int h1i = (((ib * m10) ^ (ic * m11)) & 4095) + 4096;
        const int h2i = (((ia * m20) ^ (ib * m21) ^ (ic * m22)) & 4095) + 8192;
        const int h3i = (((ia * m30) ^ (ib * m31) ^ (ic * m32)) & 4095) + 12288;
        T.k0 = __ldg((const float4*)(g_Ktab + (size_t)h0i * 512 + c));
        T.k1 = __ldg((const float4*)(g_Ktab + (size_t)h1i * 512 + c));
        T.k2 = __ldg((const float4*)(g_Ktab + (size_t)h2i * 512 + c));
        T.k3 = __ldg((const float4*)(g_Ktab + (size_t)h3i * 512 + c));
        T.v0 = __ldg((const float4*)(g_Vtab + (size_t)h0i * 128 + d));
        T.v1 = __ldg((const float4*)(g_Vtab + (size_t)h1i * 128 + d));
        T.v2 = __ldg((const float4*)(g_Vtab + (size_t)h2i * 128 + d));
        T.v3 = __ldg((const float4*)(g_Vtab + (size_t)h3i * 128 + d));
        T.q  = *(const float4*)(xBase + (size_t)t * CHq);
    };

    auto compute = [&](const Tok& T, int t, bool store) {
        float4 kr, vb;
        kr.x = (T.k0.x + T.k1.x) + (T.k2.x + T.k3.x);
        kr.y = (T.k0.y + T.k1.y) + (T.k2.y + T.k3.y);
        kr.z = (T.k0.z + T.k1.z) + (T.k2.z + T.k3.z);
        kr.w = (T.k0.w + T.k1.w) + (T.k2.w + T.k3.w);
        vb.x = (T.v0.x + T.v1.x) + (T.v2.x + T.v3.x);
        vb.y = (T.v0.y + T.v1.y) + (T.v2.y + T.v3.y);
        vb.z = (T.v0.z + T.v1.z) + (T.v2.z + T.v3.z);
        vb.w = (T.v0.w + T.v1.w) + (T.v2.w + T.v3.w);

        float p0 = T.q.x * T.q.x + T.q.y * T.q.y + T.q.z * T.q.z + T.q.w * T.q.w;
        float p1 = kr.x * kr.x + kr.y * kr.y + kr.z * kr.z + kr.w * kr.w;
        float p2 = T.q.x * kr.x * wqk4.x + T.q.y * kr.y * wqk4.y
                 + T.q.z * kr.z * wqk4.z + T.q.w * kr.w * wqk4.w;
        float p3 = vb.x * vb.x + vb.y * vb.y + vb.z * vb.z + vb.w * vb.w;

        const bool lo = (lane < 16);
        float ea = __shfl_xor_sync(0xffffffffu, p0, 16);
        float eb = __shfl_xor_sync(0xffffffffu, p2, 16);
        float aa = lo ? (p0 + ea) : (p2 + eb);
        float ec = __shfl_xor_sync(0xffffffffu, p1, 16);
        float ed = __shfl_xor_sync(0xffffffffu, p3, 16);
        float bb = lo ? (p1 + ec) : (p3 + ed);
#pragma unroll
        for (int off = 8; off; off >>= 1) {
            aa += __shfl_xor_sync(0xffffffffu, aa, off);
            bb += __shfl_xor_sync(0xffffffffu, bb, off);
        }
        const float a2 = __shfl_xor_sync(0xffffffffu, aa, 16);
        const float b2 = __shfl_xor_sync(0xffffffffu, bb, 16);
        const float sq  = lo ? aa : a2;
        const float sk  = lo ? bb : b2;
        const float sqk = lo ? a2 : aa;
        const float svb = lo ? b2 : bb;

        const float rsq   = rsqrtf(sq * inv128 + eps);
        const float rsk   = rsqrtf(sk * inv128 + eps);
        const float score = sqk * rsq * rsk * invsqrt128;
        const float gate  = __fdividef(1.f, 1.f + __expf(-score));
        const float rr    = rsqrtf(gate * gate * svb * inv128 + eps) * gate;

        float4 xn;
        xn.x = vb.x * rr * cvn4.x;  xn.y = vb.y * rr * cvn4.y;
        xn.z = vb.z * rr * cvn4.z;  xn.w = vb.w * rr * cvn4.w;

        if (store) {
            float4 y;
            y.x = cwA.x * h3.x + cwA.y * h2.x + cwA.z * h1.x + cwA.w * xn.x;
            y.y = cwB.x * h3.y + cwB.y * h2.y + cwB.z * h1.y + cwB.w * xn.y;
            y.z = cwC.x * h3.z + cwC.y * h2.z + cwC.z * h1.z + cwC.w * xn.z;
            y.w = cwD.x * h3.w + cwD.y * h2.w + cwD.z * h1.w + cwD.w * xn.w;
            y.x = __fdividef(y.x, 1.f + __expf(-y.x));
            y.y = __fdividef(y.y, 1.f + __expf(-y.y));
            y.z = __fdividef(y.z, 1.f + __expf(-y.z));
            y.w = __fdividef(y.w, 1.f + __expf(-y.w));
            float4 o;
            o.x = vb.x * gate + y.x;  o.y = vb.y * gate + y.y;
            o.z = vb.z * gate + y.z;  o.w = vb.w * gate + y.w;
            *(float4*)(oBase + (size_t)t * CHq) = o;
        }
        h3 = h2; h2 = h1; h1 = xn;
    };

    int ia = (t0 - 5 >= 0) ? __ldg(ids + idBase + t0 - 5) : 0;
    int ib = (t0 - 4 >= 0) ? __ldg(ids + idBase + t0 - 4) : 0;

    // ---- halo prologue: tokens t0-3 .. t0-1 (no store, unpipelined) ----
#pragma unroll
    for (int tt = -3; tt < 0; tt++) {
        const int t  = t0 + tt;
        const int ic = (t >= 0) ? __ldg(ids + idBase + t) : 0;
        if (t >= 0) {
            Tok P;
            gather(P, ia, ib, ic, t);
            compute(P, t, false);
        }
        ia = ib; ib = ic;
    }

    // ---- pipelined main loop: tokens t0 .. t0+R_TOK-1 ----
    int ic = __ldg(ids + idBase + t0);
    Tok cur;
    gather(cur, ia, ib, ic, t0);

    for (int tt = 0; tt < R_TOK; tt++) {
        const int t = t0 + tt;
        Tok nxt;
        int in_ = ic;
        if (tt + 1 < R_TOK) {
            in_ = __ldg(ids + idBase + t + 1);
            gather(nxt, ib, ic, in_, t + 1);   // issue before compute(cur)
        }
        compute(cur, t, true);
        ia = ib; ib = ic; ic = in_;
        cur = nxt;
    }
}

// ---------------------------------------------------------------------------
extern "C" void kernel_launch(void* const* d_in, const int* in_sizes, int n_in,
                              void* d_out, int out_size)
{
    const float* x          = (const float*)d_in[0];
    const int*   input_ids  = (const int*)  d_in[1];
    const int*   multipliers= (const int*)  d_in[2];
    const float* embedding  = (const float*)d_in[3];
    const float* val_W      = (const float*)d_in[4];
    const float* val_b      = (const float*)d_in[5];
    const float* key_W      = (const float*)d_in[6];
    const float* key_b      = (const float*)d_in[7];
    const float* normq_w    = (const float*)d_in[8];
    const float* normk_w    = (const float*)d_in[9];
    const float* conv_w     = (const float*)d_in[10];
    const float* convnorm_w = (const float*)d_in[11];
    float* out = (float*)d_out;

    dim3 gp(10, 32, 4);
    precompute_kernel<<<gp, 128>>>(embedding, val_W, key_W, val_b, key_b);

    engram_main_kernel<<<Bq * CHUNKS, 128>>>(
        x, input_ids, multipliers,
        normq_w, normk_w, conv_w, convnorm_w, out);
}